// round 6
// baseline (speedup 1.0000x reference)
#include <cuda_runtime.h>
#include <cuda_bf16.h>

#define N      512
#define NVIEWS 512
#define NBINS  512
#define MAXB   4

// Padded staging image, batches interleaved per pixel (float4).
// Rows 128B-aligned (528 px * 16B = 8448B = 66*128B). >=2-pixel zero border.
#define PW4    528
#define PH     516
#define XOFF   8              // x offset: padded col = x + 8  (>=2 margin, 8-aligned)
#define YOFF   2              // y offset

__device__ float4 g_pad4[PH * PW4];   // 4.36 MB scratch (__device__ global, allowed)

// Pre-pass: build the interleaved zero-padded image. Writes EVERY element.
__global__ void pad_kernel(const float* __restrict__ xin, int B)
{
    int idx = blockIdx.x * blockDim.x + threadIdx.x;
    if (idx >= PH * PW4) return;
    int py = idx / PW4;
    int px = idx - py * PW4;
    int ix = px - XOFF;
    int iy = py - YOFF;
    float4 v = make_float4(0.f, 0.f, 0.f, 0.f);
    if ((unsigned)ix < (unsigned)N && (unsigned)iy < (unsigned)N) {
        size_t o = (size_t)iy * N + ix;
        v.x = xin[o];
        if (B > 1) v.y = xin[o + (size_t)N * N];
        if (B > 2) v.z = xin[o + 2 * (size_t)N * N];
        if (B > 3) v.w = xin[o + 3 * (size_t)N * N];
    }
    g_pad4[idx] = v;
}

// Parallel-beam Radon forward projection, all batches fused per ray.
// Grid: (view, bin-quarter). Block: 128 threads = 4 warps.
// Each warp processes `a` bins x `b` t-offsets per iteration (a*b=32),
// shape chosen per-angle to minimize L1 line footprint of the float4 gathers.
__global__ void __launch_bounds__(128, 6)
radon_fp_kernel(float* __restrict__ out, int B)
{
    const int v = blockIdx.x;             // view / angle index
    const int q = blockIdx.y;             // bin quarter (128 bins each)

    const float dth = (float)(3.14159265358979323846 / (double)NVIEWS);
    float st, ct;
    sincosf((float)v * dth, &st, &ct);    // st >= 0 for theta in [0, pi)
    const float act = fabsf(ct);

    // ---- choose warp tile shape: a bins x b t, a*b = 32 (uniform per block) ----
    int la = 0;
    {
        float best = 3.0e38f;
        #pragma unroll
        for (int l = 0; l <= 5; ++l) {
            float af = (float)(1 << l);
            float bf = 32.0f / af;
            float rows = af * st + bf * act + 2.0f;              // y-rows touched
            float xext = (af * act + bf * st) * 16.0f + 32.0f;   // x-extent bytes
            float cost = rows * (1.0f + xext * (1.0f / 128.0f));
            if (cost < best) { best = cost; la = l; }
        }
    }
    const int a = 1 << la;      // bins per warp tile
    const int b = 32 >> la;     // t-offsets per warp tile

    const int tid  = threadIdx.x;
    const int wid  = tid >> 5;                // 0..3
    const int lane = tid & 31;
    const int ls   = lane & (a - 1);          // bin offset within tile
    const int lt   = lane >> la;              // t offset within tile
    const float ltf = (float)lt;

    const float c   = (float)(N - 1) * 0.5f;  // 255.5
    const float nst = -st;
    const float hiB = (float)N + 0.5f;        // 512.5 (window margin)

    const float ist = 1.0f / st;              // used only when st > 1e-6
    const float ict = 1.0f / ct;              // used only when |ct| > 1e-6

    const int binLo = q * (NBINS / 4);
    const int binHi = binLo + (NBINS / 4);

    for (int binBase = binLo + wid * a; binBase < binHi; binBase += 4 * a) {
        const int bin = binBase + ls;
        const float s = (float)bin - c;
        // x(t) = X0 - t*st ; y(t) = Y0 + t*ct   (t = 0..511)
        const float X0 = fmaf(s, ct, fmaf(c, st, c));
        const float Y0 = fmaf(s, st, fmaf(-c, ct, c));

        // ---- valid-t window (conservative margin: value==0 outside x,y in (-1,512)) ----
        float tlo = 0.0f, thi = (float)(N - 1);
        if (st > 1e-6f) {
            tlo = fmaxf(tlo, (X0 - hiB)  * ist);
            thi = fminf(thi, (X0 + 1.5f) * ist);
        } else if (X0 < -1.5f || X0 > hiB) {
            thi = -1.0f;
        }
        if (ct > 1e-6f) {
            tlo = fmaxf(tlo, (-1.5f - Y0) * ict);
            thi = fminf(thi, (hiB  - Y0) * ict);
        } else if (ct < -1e-6f) {
            tlo = fmaxf(tlo, (hiB  - Y0) * ict);
            thi = fminf(thi, (-1.5f - Y0) * ict);
        } else if (Y0 < -1.5f || Y0 > hiB) {
            thi = -1.0f;
        }

        // warp union of per-lane windows (keeps loop trip-count warp-uniform;
        // lanes outside their own window read the zero border -> exact)
        #pragma unroll
        for (int off = 16; off; off >>= 1) {
            tlo = fminf(tlo, __shfl_xor_sync(0xffffffffu, tlo, off));
            thi = fmaxf(thi, __shfl_xor_sync(0xffffffffu, thi, off));
        }
        const int it0 = max(0, (int)floorf(tlo));
        const int it1 = min(N - 1, (int)ceilf(thi));   // < it0 -> empty ray

        float acc0 = 0.f, acc1 = 0.f, acc2 = 0.f, acc3 = 0.f;
        #pragma unroll 2
        for (int tb = it0; tb <= it1; tb += b) {
            const int   ti = tb + lt;
            const float tf = (float)tb + ltf;
            const float xx = fmaf(tf, nst, X0);
            const float yy = fmaf(tf, ct,  Y0);
            const int fx = __float2int_rd(xx);
            const int fy = __float2int_rd(yy);
            const float wx = xx - (float)fx;
            const float wy = yy - (float)fy;
            // clamp into padded frame; clamped-away positions read only zeros.
            // t>=N overshoot lanes are redirected into the zero border (their
            // contribution must be exactly 0).
            const int x0 = (ti < N) ? max(-2, min(fx, N)) : -2;
            const int y0 = max(-2, min(fy, N));
            const int rowOff = (y0 + YOFF) * PW4;          // row index
            const float4* p = g_pad4 + (rowOff + (x0 + XOFF));
            const float4 v00 = __ldg(p);
            const float4 v10 = __ldg(p + 1);
            const float4 v01 = __ldg(p + PW4);
            const float4 v11 = __ldg(p + PW4 + 1);
            const float omx = 1.0f - wx;
            const float omy = 1.0f - wy;
            const float w00 = omx * omy;
            const float w10 = wx  * omy;
            const float w01 = omx * wy;
            const float w11 = wx  * wy;
            acc0 += fmaf(w00, v00.x, fmaf(w10, v10.x, fmaf(w01, v01.x, w11 * v11.x)));
            acc1 += fmaf(w00, v00.y, fmaf(w10, v10.y, fmaf(w01, v01.y, w11 * v11.y)));
            acc2 += fmaf(w00, v00.z, fmaf(w10, v10.z, fmaf(w01, v01.z, w11 * v11.z)));
            acc3 += fmaf(w00, v00.w, fmaf(w10, v10.w, fmaf(w01, v01.w, w11 * v11.w)));
        }

        // reduce partial sums over the b t-lanes of each bin (xor groups = same ls)
        #pragma unroll
        for (int off = 16; off >= 1; off >>= 1) {
            if (off >= a) {
                acc0 += __shfl_xor_sync(0xffffffffu, acc0, off);
                acc1 += __shfl_xor_sync(0xffffffffu, acc1, off);
                acc2 += __shfl_xor_sync(0xffffffffu, acc2, off);
                acc3 += __shfl_xor_sync(0xffffffffu, acc3, off);
            }
        }
        float* o = out + ((size_t)v * NBINS + bin);
        if (lane < a) {
            o[0] = acc0;
            if (B > 1) o[(size_t)NVIEWS * NBINS]     = acc1;
            if (B > 2) o[2 * (size_t)NVIEWS * NBINS] = acc2;
            if (B > 3) o[3 * (size_t)NVIEWS * NBINS] = acc3;
        }
    }
}

extern "C" void kernel_launch(void* const* d_in, const int* in_sizes, int n_in,
                              void* d_out, int out_size)
{
    const float* x = (const float*)d_in[0];
    int B = in_sizes[0] / (N * N);   // 4
    if (B > MAXB) B = MAXB;

    pad_kernel<<<(PH * PW4 + 255) / 256, 256>>>(x, B);

    dim3 grid(NVIEWS, 4);
    radon_fp_kernel<<<grid, 128>>>((float*)d_out, B);
}

// round 7
// speedup vs baseline: 2.0990x; 2.0990x over previous
#include <cuda_runtime.h>
#include <cuda_fp16.h>

#define N      512
#define NVIEWS 512
#define NBINS  512
#define MAXB   4

// Padded staging image: pixels stored as fp16, 4 batches interleaved, and
// DUPLICATED PAIRS: element (y, x) holds pixels (x,y) and (x+1,y) in one uint4
// (16 bytes). One LDG.128 therefore fetches both horizontal bilinear taps for
// all 4 batches. Rows 128B-aligned (528 * 16B = 66 lines). >=2-pixel border.
#define PW4    528
#define PH     516
#define XOFF   8              // padded element index = x + 8  (>=2 margin)
#define YOFF   2

__device__ uint4 g_pad[PH * PW4];   // 4.36 MB scratch (__device__ global, allowed)

// Pre-pass: build the padded pair-duplicated fp16 image. Writes EVERY element.
__global__ void pad_kernel(const float* __restrict__ xin, int B)
{
    int idx = blockIdx.x * blockDim.x + threadIdx.x;
    if (idx >= PH * PW4) return;
    int py = idx / PW4;
    int px = idx - py * PW4;
    int iy = py - YOFF;

    float p0[2] = {0.f, 0.f}, p1[2] = {0.f, 0.f}, p2[2] = {0.f, 0.f}, p3[2] = {0.f, 0.f};
    #pragma unroll
    for (int k = 0; k < 2; ++k) {
        int ix = px - XOFF + k;
        if ((unsigned)ix < (unsigned)N && (unsigned)iy < (unsigned)N) {
            size_t o = (size_t)iy * N + ix;
            p0[k] = xin[o];
            if (B > 1) p1[k] = xin[o + (size_t)N * N];
            if (B > 2) p2[k] = xin[o + 2 * (size_t)N * N];
            if (B > 3) p3[k] = xin[o + 3 * (size_t)N * N];
        }
    }
    uint4 u;
    __half2 h;
    h = __floats2half2_rn(p0[0], p1[0]); u.x = *(unsigned*)&h;  // px x,  batches 0,1
    h = __floats2half2_rn(p2[0], p3[0]); u.y = *(unsigned*)&h;  // px x,  batches 2,3
    h = __floats2half2_rn(p0[1], p1[1]); u.z = *(unsigned*)&h;  // px x+1, batches 0,1
    h = __floats2half2_rn(p2[1], p3[1]); u.w = *(unsigned*)&h;  // px x+1, batches 2,3
    g_pad[idx] = u;
}

// Parallel-beam Radon forward projection, all batches fused per ray.
// Grid: (view, bin-quarter). Block: 128 threads = 4 warps.
// Each warp processes `a` bins x `b` t-offsets per iteration (a*b=32),
// shape chosen per-angle to minimize L1 line footprint of the gathers.
__global__ void __launch_bounds__(128, 6)
radon_fp_kernel(float* __restrict__ out, int B)
{
    const int v = blockIdx.x;             // view / angle index
    const int q = blockIdx.y;             // bin quarter (128 bins each)

    const float dth = (float)(3.14159265358979323846 / (double)NVIEWS);
    float st, ct;
    sincosf((float)v * dth, &st, &ct);    // st >= 0 for theta in [0, pi)
    const float act = fabsf(ct);

    // ---- choose warp tile shape: a bins x b t, a*b = 32 (uniform per block) ----
    int la = 0;
    {
        float best = 3.0e38f;
        #pragma unroll
        for (int l = 0; l <= 5; ++l) {
            float af = (float)(1 << l);
            float bf = 32.0f / af;
            float rows = af * st + bf * act + 2.0f;              // y-rows touched
            float xext = (af * act + bf * st) * 16.0f + 32.0f;   // x-extent bytes
            float cost = rows * (1.0f + xext * (1.0f / 128.0f));
            if (cost < best) { best = cost; la = l; }
        }
    }
    const int a = 1 << la;      // bins per warp tile
    const int b = 32 >> la;     // t-offsets per warp tile

    const int tid  = threadIdx.x;
    const int wid  = tid >> 5;                // 0..3
    const int lane = tid & 31;
    const int ls   = lane & (a - 1);          // bin offset within tile
    const int lt   = lane >> la;              // t offset within tile
    const float ltf = (float)lt;

    const float c   = (float)(N - 1) * 0.5f;  // 255.5
    const float nst = -st;
    const float hiB = (float)N + 0.5f;        // 512.5 (window margin)

    const float ist = 1.0f / st;              // used only when st > 1e-6
    const float ict = 1.0f / ct;              // used only when |ct| > 1e-6

    const int binLo = q * (NBINS / 4);
    const int binHi = binLo + (NBINS / 4);

    for (int binBase = binLo + wid * a; binBase < binHi; binBase += 4 * a) {
        const int bin = binBase + ls;
        const float s = (float)bin - c;
        // x(t) = X0 - t*st ; y(t) = Y0 + t*ct   (t = 0..511)
        const float X0 = fmaf(s, ct, fmaf(c, st, c));
        const float Y0 = fmaf(s, st, fmaf(-c, ct, c));

        // ---- valid-t window (conservative margin: value==0 outside x,y in (-1,512)) ----
        float tlo = 0.0f, thi = (float)(N - 1);
        if (st > 1e-6f) {
            tlo = fmaxf(tlo, (X0 - hiB)  * ist);
            thi = fminf(thi, (X0 + 1.5f) * ist);
        } else if (X0 < -1.5f || X0 > hiB) {
            thi = -1.0f;
        }
        if (ct > 1e-6f) {
            tlo = fmaxf(tlo, (-1.5f - Y0) * ict);
            thi = fminf(thi, (hiB  - Y0) * ict);
        } else if (ct < -1e-6f) {
            tlo = fmaxf(tlo, (hiB  - Y0) * ict);
            thi = fminf(thi, (-1.5f - Y0) * ict);
        } else if (Y0 < -1.5f || Y0 > hiB) {
            thi = -1.0f;
        }

        // warp union of per-lane windows (keeps loop trip-count warp-uniform;
        // lanes outside their own window read the zero border -> exact)
        #pragma unroll
        for (int off = 16; off; off >>= 1) {
            tlo = fminf(tlo, __shfl_xor_sync(0xffffffffu, tlo, off));
            thi = fmaxf(thi, __shfl_xor_sync(0xffffffffu, thi, off));
        }
        const int it0 = max(0, (int)floorf(tlo));
        const int it1 = min(N - 1, (int)ceilf(thi));   // < it0 -> empty ray

        float acc0 = 0.f, acc1 = 0.f, acc2 = 0.f, acc3 = 0.f;
        #pragma unroll 2
        for (int tb = it0; tb <= it1; tb += b) {
            const int   ti = tb + lt;
            const float tf = (float)tb + ltf;
            const float xx = fmaf(tf, nst, X0);
            const float yy = fmaf(tf, ct,  Y0);
            const int fx = __float2int_rd(xx);
            const int fy = __float2int_rd(yy);
            const float wx = xx - (float)fx;
            const float wy = yy - (float)fy;
            // clamp into padded frame; clamped-away positions read only zeros.
            // t>=N overshoot lanes redirected into the zero border (exact 0).
            const int x0 = (ti < N) ? max(-2, min(fx, N)) : -2;
            const int y0 = max(-2, min(fy, N));
            const uint4* p = g_pad + ((y0 + YOFF) * PW4 + (x0 + XOFF));
            const uint4 t0 = __ldg(p);         // v00 (b0..3), v10 (b0..3)
            const uint4 t1 = __ldg(p + PW4);   // v01 (b0..3), v11 (b0..3)
            const float2 v00a = __half22float2(*(const __half2*)&t0.x);
            const float2 v00b = __half22float2(*(const __half2*)&t0.y);
            const float2 v10a = __half22float2(*(const __half2*)&t0.z);
            const float2 v10b = __half22float2(*(const __half2*)&t0.w);
            const float2 v01a = __half22float2(*(const __half2*)&t1.x);
            const float2 v01b = __half22float2(*(const __half2*)&t1.y);
            const float2 v11a = __half22float2(*(const __half2*)&t1.z);
            const float2 v11b = __half22float2(*(const __half2*)&t1.w);
            const float omx = 1.0f - wx;
            const float omy = 1.0f - wy;
            const float w00 = omx * omy;
            const float w10 = wx  * omy;
            const float w01 = omx * wy;
            const float w11 = wx  * wy;
            acc0 += fmaf(w00, v00a.x, fmaf(w10, v10a.x, fmaf(w01, v01a.x, w11 * v11a.x)));
            acc1 += fmaf(w00, v00a.y, fmaf(w10, v10a.y, fmaf(w01, v01a.y, w11 * v11a.y)));
            acc2 += fmaf(w00, v00b.x, fmaf(w10, v10b.x, fmaf(w01, v01b.x, w11 * v11b.x)));
            acc3 += fmaf(w00, v00b.y, fmaf(w10, v10b.y, fmaf(w01, v01b.y, w11 * v11b.y)));
        }

        // reduce partial sums over the b t-lanes of each bin (xor groups = same ls)
        #pragma unroll
        for (int off = 16; off >= 1; off >>= 1) {
            if (off >= a) {
                acc0 += __shfl_xor_sync(0xffffffffu, acc0, off);
                acc1 += __shfl_xor_sync(0xffffffffu, acc1, off);
                acc2 += __shfl_xor_sync(0xffffffffu, acc2, off);
                acc3 += __shfl_xor_sync(0xffffffffu, acc3, off);
            }
        }
        float* o = out + ((size_t)v * NBINS + bin);
        if (lane < a) {
            o[0] = acc0;
            if (B > 1) o[(size_t)NVIEWS * NBINS]     = acc1;
            if (B > 2) o[2 * (size_t)NVIEWS * NBINS] = acc2;
            if (B > 3) o[3 * (size_t)NVIEWS * NBINS] = acc3;
        }
    }
}

extern "C" void kernel_launch(void* const* d_in, const int* in_sizes, int n_in,
                              void* d_out, int out_size)
{
    const float* x = (const float*)d_in[0];
    int B = in_sizes[0] / (N * N);   // 4
    if (B > MAXB) B = MAXB;

    pad_kernel<<<(PH * PW4 + 255) / 256, 256>>>(x, B);

    dim3 grid(NVIEWS, 4);
    radon_fp_kernel<<<grid, 128>>>((float*)d_out, B);
}

// round 8
// speedup vs baseline: 2.3894x; 1.1383x over previous
#include <cuda_runtime.h>
#include <cuda_fp16.h>

#define N      512
#define NVIEWS 512
#define NBINS  512
#define MAXB   4

// Padded staging image: pixels stored as fp16, 4 batches interleaved, and
// DUPLICATED PAIRS: element (y, x) holds pixels (x,y) and (x+1,y) in one uint4
// (16 bytes). One LDG.128 therefore fetches both horizontal bilinear taps for
// all 4 batches. Rows 128B-aligned (528 * 16B = 66 lines). >=2-pixel border.
#define PW4    528
#define PH     516
#define XOFF   8              // padded element index = x + 8  (>=2 margin)
#define YOFF   2

__device__ uint4 g_pad[PH * PW4];   // 4.36 MB scratch (__device__ global, allowed)

// Pre-pass: build the padded pair-duplicated fp16 image. Writes EVERY element.
__global__ void pad_kernel(const float* __restrict__ xin, int B)
{
    int idx = blockIdx.x * blockDim.x + threadIdx.x;
    if (idx >= PH * PW4) return;
    int py = idx / PW4;
    int px = idx - py * PW4;
    int iy = py - YOFF;

    float p0[2] = {0.f, 0.f}, p1[2] = {0.f, 0.f}, p2[2] = {0.f, 0.f}, p3[2] = {0.f, 0.f};
    #pragma unroll
    for (int k = 0; k < 2; ++k) {
        int ix = px - XOFF + k;
        if ((unsigned)ix < (unsigned)N && (unsigned)iy < (unsigned)N) {
            size_t o = (size_t)iy * N + ix;
            p0[k] = xin[o];
            if (B > 1) p1[k] = xin[o + (size_t)N * N];
            if (B > 2) p2[k] = xin[o + 2 * (size_t)N * N];
            if (B > 3) p3[k] = xin[o + 3 * (size_t)N * N];
        }
    }
    uint4 u;
    __half2 h;
    h = __floats2half2_rn(p0[0], p1[0]); u.x = *(unsigned*)&h;  // px x,  batches 0,1
    h = __floats2half2_rn(p2[0], p3[0]); u.y = *(unsigned*)&h;  // px x,  batches 2,3
    h = __floats2half2_rn(p0[1], p1[1]); u.z = *(unsigned*)&h;  // px x+1, batches 0,1
    h = __floats2half2_rn(p2[1], p3[1]); u.w = *(unsigned*)&h;  // px x+1, batches 2,3
    g_pad[idx] = u;
}

// Parallel-beam Radon forward projection, all batches fused per ray.
// Grid: (view, bin-quarter). Block: 128 threads = 4 warps.
// Two lane-mapping modes per angle:
//  - |ct| >= 0.64 ("phase mode"): one lane per bin, per-lane integer t-phase
//    delta_i = -round(i*tan(theta)) aligns all 32 simultaneous samples onto
//    ~one image row -> minimal L1 line footprint. Coverage exact (each lane
//    sums its full t-window, phase-shifted; out-of-range t masked).
//  - otherwise: adaptive a bins x b t warp tile (a*b=32) minimizing footprint.
__global__ void __launch_bounds__(128, 6)
radon_fp_kernel(float* __restrict__ out, int B)
{
    const int v = blockIdx.x;             // view / angle index
    const int q = blockIdx.y;             // bin quarter (128 bins each)

    const float dth = (float)(3.14159265358979323846 / (double)NVIEWS);
    float st, ct;
    sincosf((float)v * dth, &st, &ct);    // st >= 0 for theta in [0, pi)
    const float act = fabsf(ct);
    const bool phaseMode = (act >= 0.64f);

    // ---- choose warp tile shape: a bins x b t, a*b = 32 (uniform per block) ----
    int la = 5;
    if (!phaseMode) {
        float best = 3.0e38f;
        #pragma unroll
        for (int l = 0; l <= 5; ++l) {
            float af = (float)(1 << l);
            float bf = 32.0f / af;
            float rows = af * st + bf * act + 2.0f;              // y-rows touched
            float xext = (af * act + bf * st) * 16.0f + 32.0f;   // x-extent bytes
            float cost = rows * (1.0f + xext * (1.0f / 128.0f));
            if (cost < best) { best = cost; la = l; }
        }
    }
    const int a = 1 << la;      // bins per warp tile
    const int b = 32 >> la;     // t-offsets per warp tile

    const int tid  = threadIdx.x;
    const int wid  = tid >> 5;                // 0..3
    const int lane = tid & 31;
    const int ls   = lane & (a - 1);          // bin offset within tile
    const int lt   = lane >> la;              // t offset within tile
    const float ltf = (float)lt;

    const float c   = (float)(N - 1) * 0.5f;  // 255.5
    const float nst = -st;
    const float hiB = (float)N + 0.5f;        // 512.5 (window margin)

    const float ist = 1.0f / st;              // used only when st > 1e-6
    const float ict = 1.0f / ct;              // used only when |ct| > 1e-6

    // per-lane t-phase (phase mode only): keeps warp's samples row-aligned
    int dlt = 0;
    if (phaseMode) dlt = -(int)roundf((float)ls * st * ict);
    const float dltf = (float)dlt;

    const int binLo = q * (NBINS / 4);
    const int binHi = binLo + (NBINS / 4);

    for (int binBase = binLo + wid * a; binBase < binHi; binBase += 4 * a) {
        const int bin = binBase + ls;
        const float s = (float)bin - c;
        // x(t) = X0 - t*st ; y(t) = Y0 + t*ct   (t = 0..511). With t = k + dlt:
        const float X0 = fmaf(s, ct, fmaf(c, st, c)) + dltf * nst;
        const float Y0 = fmaf(s, st, fmaf(-c, ct, c)) + dltf * ct;

        // ---- valid-t window in t-units (value==0 outside x,y in (-1,512)) ----
        float tlo = 0.0f, thi = (float)(N - 1);
        {
            // compute window on actual t, then shift to k-space (k = t - dlt)
            const float Xr = X0 - dltf * nst;   // un-shifted X0
            const float Yr = Y0 - dltf * ct;    // un-shifted Y0
            if (st > 1e-6f) {
                tlo = fmaxf(tlo, (Xr - hiB)  * ist);
                thi = fminf(thi, (Xr + 1.5f) * ist);
            } else if (Xr < -1.5f || Xr > hiB) {
                thi = -1.0f;
            }
            if (ct > 1e-6f) {
                tlo = fmaxf(tlo, (-1.5f - Yr) * ict);
                thi = fminf(thi, (hiB  - Yr) * ict);
            } else if (ct < -1e-6f) {
                tlo = fmaxf(tlo, (hiB  - Yr) * ict);
                thi = fminf(thi, (-1.5f - Yr) * ict);
            } else if (Yr < -1.5f || Yr > hiB) {
                thi = -1.0f;
            }
            tlo -= dltf;
            thi -= dltf;
        }

        // warp union of per-lane k-windows (keeps loop trip-count warp-uniform;
        // lanes outside their own window read the zero border -> exact)
        #pragma unroll
        for (int off = 16; off; off >>= 1) {
            tlo = fminf(tlo, __shfl_xor_sync(0xffffffffu, tlo, off));
            thi = fmaxf(thi, __shfl_xor_sync(0xffffffffu, thi, off));
        }
        const int it0 = max(-64, (int)floorf(tlo));
        const int it1 = min(N - 1 + 64, (int)ceilf(thi));   // < it0 -> empty

        float acc0 = 0.f, acc1 = 0.f, acc2 = 0.f, acc3 = 0.f;
        #pragma unroll 2
        for (int tb = it0; tb <= it1; tb += b) {
            const int   tmask = tb + lt + dlt;     // actual t of this sample
            const float tf = (float)tb + ltf;
            const float xx = fmaf(tf, nst, X0);
            const float yy = fmaf(tf, ct,  Y0);
            const int fx = __float2int_rd(xx);
            const int fy = __float2int_rd(yy);
            const float wx = xx - (float)fx;
            const float wy = yy - (float)fy;
            // clamp into padded frame; clamped-away positions read only zeros.
            // t outside [0,N) redirected into the zero border (exact 0).
            const int x0 = ((unsigned)tmask < (unsigned)N) ? max(-2, min(fx, N)) : -2;
            const int y0 = max(-2, min(fy, N));
            const uint4* p = g_pad + ((y0 + YOFF) * PW4 + (x0 + XOFF));
            const uint4 t0 = __ldg(p);         // v00 (b0..3), v10 (b0..3)
            const uint4 t1 = __ldg(p + PW4);   // v01 (b0..3), v11 (b0..3)
            const float2 v00a = __half22float2(*(const __half2*)&t0.x);
            const float2 v00b = __half22float2(*(const __half2*)&t0.y);
            const float2 v10a = __half22float2(*(const __half2*)&t0.z);
            const float2 v10b = __half22float2(*(const __half2*)&t0.w);
            const float2 v01a = __half22float2(*(const __half2*)&t1.x);
            const float2 v01b = __half22float2(*(const __half2*)&t1.y);
            const float2 v11a = __half22float2(*(const __half2*)&t1.z);
            const float2 v11b = __half22float2(*(const __half2*)&t1.w);
            const float omx = 1.0f - wx;
            const float omy = 1.0f - wy;
            const float w00 = omx * omy;
            const float w10 = wx  * omy;
            const float w01 = omx * wy;
            const float w11 = wx  * wy;
            acc0 += fmaf(w00, v00a.x, fmaf(w10, v10a.x, fmaf(w01, v01a.x, w11 * v11a.x)));
            acc1 += fmaf(w00, v00a.y, fmaf(w10, v10a.y, fmaf(w01, v01a.y, w11 * v11a.y)));
            acc2 += fmaf(w00, v00b.x, fmaf(w10, v10b.x, fmaf(w01, v01b.x, w11 * v11b.x)));
            acc3 += fmaf(w00, v00b.y, fmaf(w10, v10b.y, fmaf(w01, v01b.y, w11 * v11b.y)));
        }

        // reduce partial sums over the b t-lanes of each bin (xor groups = same ls)
        // (phase mode: a=32 -> no reduction, each lane owns its bin)
        #pragma unroll
        for (int off = 16; off >= 1; off >>= 1) {
            if (off >= a) {
                acc0 += __shfl_xor_sync(0xffffffffu, acc0, off);
                acc1 += __shfl_xor_sync(0xffffffffu, acc1, off);
                acc2 += __shfl_xor_sync(0xffffffffu, acc2, off);
                acc3 += __shfl_xor_sync(0xffffffffu, acc3, off);
            }
        }
        float* o = out + ((size_t)v * NBINS + bin);
        if (lane < a) {
            o[0] = acc0;
            if (B > 1) o[(size_t)NVIEWS * NBINS]     = acc1;
            if (B > 2) o[2 * (size_t)NVIEWS * NBINS] = acc2;
            if (B > 3) o[3 * (size_t)NVIEWS * NBINS] = acc3;
        }
    }
}

extern "C" void kernel_launch(void* const* d_in, const int* in_sizes, int n_in,
                              void* d_out, int out_size)
{
    const float* x = (const float*)d_in[0];
    int B = in_sizes[0] / (N * N);   // 4
    if (B > MAXB) B = MAXB;

    pad_kernel<<<(PH * PW4 + 255) / 256, 256>>>(x, B);

    dim3 grid(NVIEWS, 4);
    radon_fp_kernel<<<grid, 128>>>((float*)d_out, B);
}

// round 9
// speedup vs baseline: 2.4158x; 1.0110x over previous
#include <cuda_runtime.h>
#include <cuda_fp16.h>

#define N      512
#define NVIEWS 512
#define NBINS  512
#define MAXB   4

// Padded staging image: pixels stored as fp16, 4 batches interleaved, and
// DUPLICATED PAIRS: element (y, x) holds pixels (x,y) and (x+1,y) in one uint4
// (16 bytes). One LDG.128 therefore fetches both horizontal bilinear taps for
// all 4 batches. Rows 128B-aligned (528 * 16B = 66 lines). >=2-pixel border.
#define PW4    528
#define PH     516
#define XOFF   8              // padded element index = x + 8  (>=2 margin)
#define YOFF   2

__device__ uint4 g_pad[PH * PW4];   // 4.36 MB scratch (__device__ global, allowed)

// ---- packed f32x2 helpers (sm_103a FFMA2 via PTX) ----
__device__ __forceinline__ unsigned long long f32x2_pack(float lo, float hi) {
    unsigned long long r;
    asm("mov.b64 %0, {%1, %2};" : "=l"(r) : "f"(lo), "f"(hi));
    return r;
}
__device__ __forceinline__ void f32x2_unpack(unsigned long long v, float& lo, float& hi) {
    asm("mov.b64 {%0, %1}, %2;" : "=f"(lo), "=f"(hi) : "l"(v));
}
__device__ __forceinline__ unsigned long long f32x2_fma(unsigned long long a,
                                                        unsigned long long b,
                                                        unsigned long long c) {
    unsigned long long d;
    asm("fma.rn.f32x2 %0, %1, %2, %3;" : "=l"(d) : "l"(a), "l"(b), "l"(c));
    return d;
}
__device__ __forceinline__ unsigned long long h2_to_f32x2(unsigned h2bits) {
    const float2 f = __half22float2(*(const __half2*)&h2bits);
    return f32x2_pack(f.x, f.y);
}

// Pre-pass: build the padded pair-duplicated fp16 image. Writes EVERY element.
__global__ void pad_kernel(const float* __restrict__ xin, int B)
{
    int idx = blockIdx.x * blockDim.x + threadIdx.x;
    if (idx >= PH * PW4) return;
    int py = idx / PW4;
    int px = idx - py * PW4;
    int iy = py - YOFF;

    float p0[2] = {0.f, 0.f}, p1[2] = {0.f, 0.f}, p2[2] = {0.f, 0.f}, p3[2] = {0.f, 0.f};
    #pragma unroll
    for (int k = 0; k < 2; ++k) {
        int ix = px - XOFF + k;
        if ((unsigned)ix < (unsigned)N && (unsigned)iy < (unsigned)N) {
            size_t o = (size_t)iy * N + ix;
            p0[k] = xin[o];
            if (B > 1) p1[k] = xin[o + (size_t)N * N];
            if (B > 2) p2[k] = xin[o + 2 * (size_t)N * N];
            if (B > 3) p3[k] = xin[o + 3 * (size_t)N * N];
        }
    }
    uint4 u;
    __half2 h;
    h = __floats2half2_rn(p0[0], p1[0]); u.x = *(unsigned*)&h;  // px x,  batches 0,1
    h = __floats2half2_rn(p2[0], p3[0]); u.y = *(unsigned*)&h;  // px x,  batches 2,3
    h = __floats2half2_rn(p0[1], p1[1]); u.z = *(unsigned*)&h;  // px x+1, batches 0,1
    h = __floats2half2_rn(p2[1], p3[1]); u.w = *(unsigned*)&h;  // px x+1, batches 2,3
    g_pad[idx] = u;
}

// Parallel-beam Radon forward projection, all batches fused per ray.
// Grid: (view, bin-quarter). Block: 128 threads = 4 warps.
// Two lane-mapping modes per angle:
//  - |ct| >= 0.5 ("phase mode"): one lane per bin, per-lane integer t-phase
//    delta_i = -round(i*tan(theta)) aligns all 32 simultaneous samples onto
//    ~one image row -> minimal L1 line footprint. Coverage exact.
//  - otherwise: adaptive a bins x b t warp tile (a*b=32) minimizing footprint.
__global__ void __launch_bounds__(128, 6)
radon_fp_kernel(float* __restrict__ out, int B)
{
    const int v = blockIdx.x;             // view / angle index
    const int q = blockIdx.y;             // bin quarter (128 bins each)

    const float dth = (float)(3.14159265358979323846 / (double)NVIEWS);
    float st, ct;
    sincosf((float)v * dth, &st, &ct);    // st >= 0 for theta in [0, pi)
    const float act = fabsf(ct);
    const bool phaseMode = (act >= 0.5f);

    // ---- choose warp tile shape: a bins x b t, a*b = 32 (uniform per block) ----
    int la = 5;
    if (!phaseMode) {
        float best = 3.0e38f;
        #pragma unroll
        for (int l = 0; l <= 5; ++l) {
            float af = (float)(1 << l);
            float bf = 32.0f / af;
            float rows = af * st + bf * act + 2.0f;              // y-rows touched
            float xext = (af * act + bf * st) * 16.0f + 32.0f;   // x-extent bytes
            float cost = rows * (1.0f + xext * (1.0f / 128.0f));
            if (cost < best) { best = cost; la = l; }
        }
    }
    const int a = 1 << la;      // bins per warp tile
    const int b = 32 >> la;     // t-offsets per warp tile

    const int tid  = threadIdx.x;
    const int wid  = tid >> 5;                // 0..3
    const int lane = tid & 31;
    const int ls   = lane & (a - 1);          // bin offset within tile
    const int lt   = lane >> la;              // t offset within tile
    const float ltf = (float)lt;

    const float c   = (float)(N - 1) * 0.5f;  // 255.5
    const float nst = -st;
    const float hiB = (float)N + 0.5f;        // 512.5 (window margin)

    const float ist = 1.0f / st;              // used only when st > 1e-6
    const float ict = 1.0f / ct;              // used only when |ct| > 1e-6

    // per-lane t-phase (phase mode only): keeps warp's samples row-aligned
    int dlt = 0;
    if (phaseMode) dlt = -(int)roundf((float)ls * st * ict);
    const float dltf = (float)dlt;

    const int binLo = q * (NBINS / 4);
    const int binHi = binLo + (NBINS / 4);

    for (int binBase = binLo + wid * a; binBase < binHi; binBase += 4 * a) {
        const int bin = binBase + ls;
        const float s = (float)bin - c;
        // x(t) = X0 - t*st ; y(t) = Y0 + t*ct   (t = 0..511). With t = k + dlt:
        const float X0 = fmaf(s, ct, fmaf(c, st, c)) + dltf * nst;
        const float Y0 = fmaf(s, st, fmaf(-c, ct, c)) + dltf * ct;

        // ---- valid-t window in t-units (value==0 outside x,y in (-1,512)) ----
        float tlo = 0.0f, thi = (float)(N - 1);
        {
            // compute window on actual t, then shift to k-space (k = t - dlt)
            const float Xr = X0 - dltf * nst;   // un-shifted X0
            const float Yr = Y0 - dltf * ct;    // un-shifted Y0
            if (st > 1e-6f) {
                tlo = fmaxf(tlo, (Xr - hiB)  * ist);
                thi = fminf(thi, (Xr + 1.5f) * ist);
            } else if (Xr < -1.5f || Xr > hiB) {
                thi = -1.0f;
            }
            if (ct > 1e-6f) {
                tlo = fmaxf(tlo, (-1.5f - Yr) * ict);
                thi = fminf(thi, (hiB  - Yr) * ict);
            } else if (ct < -1e-6f) {
                tlo = fmaxf(tlo, (hiB  - Yr) * ict);
                thi = fminf(thi, (-1.5f - Yr) * ict);
            } else if (Yr < -1.5f || Yr > hiB) {
                thi = -1.0f;
            }
            tlo -= dltf;
            thi -= dltf;
        }

        // warp union of per-lane k-windows (keeps loop trip-count warp-uniform;
        // lanes outside their own window read the zero border -> exact)
        #pragma unroll
        for (int off = 16; off; off >>= 1) {
            tlo = fminf(tlo, __shfl_xor_sync(0xffffffffu, tlo, off));
            thi = fmaxf(thi, __shfl_xor_sync(0xffffffffu, thi, off));
        }
        const int it0 = max(-64, (int)floorf(tlo));
        const int it1 = min(N - 1 + 64, (int)ceilf(thi));   // < it0 -> empty

        unsigned long long acc01 = f32x2_pack(0.f, 0.f);
        unsigned long long acc23 = acc01;
        #pragma unroll 2
        for (int tb = it0; tb <= it1; tb += b) {
            const int   tmask = tb + lt + dlt;     // actual t of this sample
            const float tf = (float)tb + ltf;
            const float xx = fmaf(tf, nst, X0);
            const float yy = fmaf(tf, ct,  Y0);
            const int fx = __float2int_rd(xx);
            const int fy = __float2int_rd(yy);
            const float wx = xx - (float)fx;
            const float wy = yy - (float)fy;
            // clamp into padded frame; clamped-away positions read only zeros.
            // t outside [0,N) redirected into the zero border (exact 0).
            const int x0 = ((unsigned)tmask < (unsigned)N) ? max(-2, min(fx, N)) : -2;
            const int y0 = max(-2, min(fy, N));
            const uint4* p = g_pad + ((y0 + YOFF) * PW4 + (x0 + XOFF));
            const uint4 t0 = __ldg(p);         // v00 (b0..3), v10 (b0..3)
            const uint4 t1 = __ldg(p + PW4);   // v01 (b0..3), v11 (b0..3)
            const unsigned long long v00a = h2_to_f32x2(t0.x);
            const unsigned long long v00b = h2_to_f32x2(t0.y);
            const unsigned long long v10a = h2_to_f32x2(t0.z);
            const unsigned long long v10b = h2_to_f32x2(t0.w);
            const unsigned long long v01a = h2_to_f32x2(t1.x);
            const unsigned long long v01b = h2_to_f32x2(t1.y);
            const unsigned long long v11a = h2_to_f32x2(t1.z);
            const unsigned long long v11b = h2_to_f32x2(t1.w);
            const float omx = 1.0f - wx;
            const float omy = 1.0f - wy;
            const unsigned long long w00 = f32x2_pack(omx * omy, omx * omy);
            const unsigned long long w10 = f32x2_pack(wx  * omy, wx  * omy);
            const unsigned long long w01 = f32x2_pack(omx * wy,  omx * wy);
            const unsigned long long w11 = f32x2_pack(wx  * wy,  wx  * wy);
            acc01 = f32x2_fma(w00, v00a, acc01);
            acc23 = f32x2_fma(w00, v00b, acc23);
            acc01 = f32x2_fma(w10, v10a, acc01);
            acc23 = f32x2_fma(w10, v10b, acc23);
            acc01 = f32x2_fma(w01, v01a, acc01);
            acc23 = f32x2_fma(w01, v01b, acc23);
            acc01 = f32x2_fma(w11, v11a, acc01);
            acc23 = f32x2_fma(w11, v11b, acc23);
        }

        float acc0, acc1, acc2, acc3;
        f32x2_unpack(acc01, acc0, acc1);
        f32x2_unpack(acc23, acc2, acc3);

        // reduce partial sums over the b t-lanes of each bin (xor groups = same ls)
        // (phase mode: a=32 -> no reduction, each lane owns its bin)
        #pragma unroll
        for (int off = 16; off >= 1; off >>= 1) {
            if (off >= a) {
                acc0 += __shfl_xor_sync(0xffffffffu, acc0, off);
                acc1 += __shfl_xor_sync(0xffffffffu, acc1, off);
                acc2 += __shfl_xor_sync(0xffffffffu, acc2, off);
                acc3 += __shfl_xor_sync(0xffffffffu, acc3, off);
            }
        }
        float* o = out + ((size_t)v * NBINS + bin);
        if (lane < a) {
            o[0] = acc0;
            if (B > 1) o[(size_t)NVIEWS * NBINS]     = acc1;
            if (B > 2) o[2 * (size_t)NVIEWS * NBINS] = acc2;
            if (B > 3) o[3 * (size_t)NVIEWS * NBINS] = acc3;
        }
    }
}

extern "C" void kernel_launch(void* const* d_in, const int* in_sizes, int n_in,
                              void* d_out, int out_size)
{
    const float* x = (const float*)d_in[0];
    int B = in_sizes[0] / (N * N);   // 4
    if (B > MAXB) B = MAXB;

    pad_kernel<<<(PH * PW4 + 255) / 256, 256>>>(x, B);

    dim3 grid(NVIEWS, 4);
    radon_fp_kernel<<<grid, 128>>>((float*)d_out, B);
}